// round 10
// baseline (speedup 1.0000x reference)
#include <cuda_runtime.h>
#include <cuda_bf16.h>
#include <cstdint>
#include <math.h>

#define TOK   8192
#define DIM   2048
#define NEXP  8
#define EDIM  1024
#define KFLAT 8192

// ---------------- static device scratch ----------------
__device__ float g_Xr [(size_t)TOK * DIM];          // rna(x)
__device__ float g_WuT[(size_t)NEXP * EDIM * DIM];  // [e][f][d]
__device__ float g_WdT[(size_t)DIM * KFLAT];        // [n][e*1024+f]
__device__ float g_Hs [(size_t)TOK * KFLAT];        // rna(p*gelu(..))
__device__ float g_Pr [(size_t)TOK * NEXP];

// ---------------- helpers ----------------
__device__ __forceinline__ uint32_t smem_u32(const void* p) {
    uint32_t a;
    asm("{ .reg .u64 t; cvta.to.shared.u64 t, %1; cvt.u32.u64 %0, t; }" : "=r"(a) : "l"(p));
    return a;
}
__device__ __forceinline__ float rna_tf32(float x) {
    uint32_t u;
    asm("cvt.rna.tf32.f32 %0, %1;" : "=r"(u) : "f"(x));
    return __uint_as_float(u);
}
__device__ __forceinline__ float gelu_t(float h) {
    float u  = 0.7978845608028654f * (h + 0.044715f * h * h * h);
    float ex = __expf(2.0f * u);
    float th = 1.0f - __fdividef(2.0f, ex + 1.0f);
    return 0.5f * h * (1.0f + th);
}
__device__ __forceinline__ void cpasync16(uint32_t dst, const float* src) {
    asm volatile("cp.async.cg.shared.global [%0], [%1], 16;" :: "r"(dst), "l"(src));
}
__device__ __forceinline__ void ldsm4(uint32_t* r, uint32_t a) {
    asm volatile("ldmatrix.sync.aligned.m8n8.x4.shared.b16 {%0,%1,%2,%3}, [%4];"
                 : "=r"(r[0]), "=r"(r[1]), "=r"(r[2]), "=r"(r[3]) : "r"(a));
}
__device__ __forceinline__ void mma8(float* d, const uint32_t* a, uint32_t b0, uint32_t b1) {
    asm volatile(
        "mma.sync.aligned.m16n8k8.row.col.f32.tf32.tf32.f32 "
        "{%0,%1,%2,%3}, {%4,%5,%6,%7}, {%8,%9}, {%0,%1,%2,%3};"
        : "+f"(d[0]), "+f"(d[1]), "+f"(d[2]), "+f"(d[3])
        : "r"(a[0]), "r"(a[1]), "r"(a[2]), "r"(a[3]), "r"(b0), "r"(b1));
}

// ---------------- prep kernels ----------------
__global__ void rna_copy_kernel(const float* __restrict__ in, float* __restrict__ out, int n4) {
    int i = blockIdx.x * blockDim.x + threadIdx.x;
    int st = gridDim.x * blockDim.x;
    const float4* i4 = (const float4*)in;
    float4* o4 = (float4*)out;
    for (; i < n4; i += st) {
        float4 v = i4[i];
        v.x = rna_tf32(v.x); v.y = rna_tf32(v.y);
        v.z = rna_tf32(v.z); v.w = rna_tf32(v.w);
        o4[i] = v;
    }
}

// out[z*outE + c*outRow + r] = rna(in[z*inE + r*C + c])
__global__ void transpose_rna_kernel(const float* __restrict__ in, float* __restrict__ out,
                                     int R, int C, size_t inE, size_t outE, int outRow) {
    __shared__ float tile[32][33];
    const float* ip = in + (size_t)blockIdx.z * inE;
    float* op = out + (size_t)blockIdx.z * outE;
    int c0 = blockIdx.x * 32, r0 = blockIdx.y * 32;
#pragma unroll
    for (int i = threadIdx.y; i < 32; i += 8)
        tile[i][threadIdx.x] = ip[(size_t)(r0 + i) * C + c0 + threadIdx.x];
    __syncthreads();
#pragma unroll
    for (int i = threadIdx.y; i < 32; i += 8)
        op[(size_t)(c0 + i) * outRow + r0 + threadIdx.x] = rna_tf32(tile[threadIdx.x][i]);
}

// router with Wr cached in smem (pad-9 layout, conflict-free)
#define RTR_SMEM (2048 * 9 * 4)
__global__ void router_kernel(const float* __restrict__ x, const float* __restrict__ Wr,
                              const float* __restrict__ br, float* __restrict__ probs) {
    extern __shared__ float ws[];
    int tid = threadIdx.x;
    for (int i = tid; i < DIM * 8; i += 256) {
        int k = i >> 3, e = i & 7;
        ws[k * 9 + e] = Wr[i];
    }
    __syncthreads();
    int t = blockIdx.x * 8 + (tid >> 5);
    int lid = tid & 31;
    const float* xr = x + (size_t)t * DIM;
    float acc[8];
#pragma unroll
    for (int e = 0; e < 8; e++) acc[e] = 0.f;
    for (int k = lid; k < DIM; k += 32) {
        float xv = xr[k];
        const float* w = ws + k * 9;
#pragma unroll
        for (int e = 0; e < 8; e++) acc[e] += xv * w[e];
    }
#pragma unroll
    for (int e = 0; e < 8; e++)
#pragma unroll
        for (int o = 16; o > 0; o >>= 1) acc[e] += __shfl_xor_sync(0xffffffffu, acc[e], o);
    if (lid == 0) {
        float m = -1e30f;
#pragma unroll
        for (int e = 0; e < 8; e++) { acc[e] += br[e]; m = fmaxf(m, acc[e]); }
        float s = 0.f;
#pragma unroll
        for (int e = 0; e < 8; e++) { acc[e] = expf(acc[e] - m); s += acc[e]; }
        float inv = 1.f / s;
#pragma unroll
        for (int e = 0; e < 8; e++) probs[(size_t)t * 8 + e] = acc[e] * inv;
    }
}

// ---------------- tf32 mma.sync GEMM ----------------
// CTA tile 256(M) x 128(N), 256 threads = 8 warps, warp grid 4(M) x 2(N),
// warp tile 64x64 (128 accum regs/thread, <=255 reg cap at 256 thr/CTA).
// K staged 32 floats/iter, 4-stage cp.async pipeline, wait_group 2.
// stage: A 256 rows * 144B = 36864 + B 128 rows * 144B = 18432 -> 55296B
#define STG_B     55296
#define SMEM_SZ   221184     // 4 * 55296

// MODE 0: Hs = rna(p[t,e0] * gelu(A@B^T + bu))   A=Xr[8192,2048], B=WuT rows
// MODE 1: out = A@B^T + sum_e p_e*bd_e + x       A=Hs[8192,8192], B=WdT rows
template<int MODE>
__global__ void __launch_bounds__(256, 1) moe_gemm(
    const float* __restrict__ A, const float* __restrict__ Bm, int K,
    const float* __restrict__ probs, const float* __restrict__ bias,
    const float* __restrict__ xres, float* __restrict__ outp)
{
    extern __shared__ float smem[];
    uint32_t sb = smem_u32(smem);
    const int tid = threadIdx.x, wid = tid >> 5, lid = tid & 31;
    const int wm = wid & 3, wn = wid >> 2;          // warp grid 4(M) x 2(N)
    const int m0 = blockIdx.y * 256, n0 = blockIdx.x * 128;
    const int g = lid >> 2, i4 = lid & 3;

    // ---- per-thread fragment smem byte offsets within a stage ----
    const uint32_t aoff = (uint32_t)((wm * 64 + (lid & 15)) * 144 + ((lid >> 4) * 16));
    const uint32_t boff = (uint32_t)(36864 +
        (wn * 64 + ((lid >> 4) & 1) * 8 + (lid & 7)) * 144 + (((lid >> 3) & 1) * 16));

    float d[4][8][4];
#pragma unroll
    for (int a = 0; a < 4; a++)
#pragma unroll
        for (int b = 0; b < 8; b++)
#pragma unroll
            for (int c = 0; c < 4; c++) d[a][b][c] = 0.f;

    const float* Ab = A + (size_t)m0 * K;
    const float* Bb = Bm + (size_t)n0 * K;

    // loader: 3072 16B chunks per stage, 12 per thread (256 threads)
    auto load_stage = [&](int st, int kt) {
        uint32_t base = sb + st * STG_B;
        const float* Ag = Ab + kt * 32;
        const float* Bg = Bb + kt * 32;
#pragma unroll
        for (int q = 0; q < 12; q++) {
            int ci = q * 256 + tid;
            if (ci < 2048) {
                int r = ci >> 3, c = ci & 7;
                cpasync16(base + r * 144 + c * 16, Ag + (size_t)r * K + c * 4);
            } else {
                int c2 = ci - 2048;
                int r = c2 >> 3, c = c2 & 7;
                cpasync16(base + 36864 + r * 144 + c * 16, Bg + (size_t)r * K + c * 4);
            }
        }
    };

    const int iters = K >> 5;
    load_stage(0, 0);
    asm volatile("cp.async.commit_group;" ::: "memory");
    load_stage(1, 1);
    asm volatile("cp.async.commit_group;" ::: "memory");
    load_stage(2, 2);
    asm volatile("cp.async.commit_group;" ::: "memory");

    for (int kt = 0; kt < iters; kt++) {
        asm volatile("cp.async.wait_group 2;" ::: "memory");
        __syncthreads();
        // prefetch stage kt+3 into buffer (kt+3)&3 == (kt-1)&3; safe after sync.
        if (kt + 3 < iters) {
            load_stage((kt + 3) & 3, kt + 3);
        }
        asm volatile("cp.async.commit_group;" ::: "memory");

        uint32_t base = sb + (kt & 3) * STG_B;
#pragma unroll
        for (int kk = 0; kk < 4; kk++) {
            uint32_t af[4][4], bf[4][4];
#pragma unroll
            for (int mt = 0; mt < 4; mt++)
                ldsm4(af[mt], base + aoff + mt * (16 * 144) + kk * 32);
#pragma unroll
            for (int P = 0; P < 4; P++)
                ldsm4(bf[P], base + boff + P * (16 * 144) + kk * 32);
#pragma unroll
            for (int mt = 0; mt < 4; mt++)
#pragma unroll
                for (int P = 0; P < 4; P++) {
                    mma8(d[mt][2 * P],     af[mt], bf[P][0], bf[P][1]);
                    mma8(d[mt][2 * P + 1], af[mt], bf[P][2], bf[P][3]);
                }
        }
    }

    // ---- epilogue (constants straight from L2; once per CTA) ----
    if (MODE == 0) {
        int e0 = n0 >> 10;
#pragma unroll
        for (int mt = 0; mt < 4; mt++)
#pragma unroll
            for (int h = 0; h < 2; h++) {
                int rl = wm * 64 + mt * 16 + h * 8 + g;
                float p = probs[(size_t)(m0 + rl) * 8 + e0];
                float* dst = outp + (size_t)(m0 + rl) * KFLAT + n0;
                const float* bu = bias + (size_t)e0 * EDIM + (n0 & 1023);
#pragma unroll
                for (int nt = 0; nt < 8; nt++) {
                    int nl = wn * 64 + nt * 8 + i4 * 2;
                    float2 v;
                    v.x = rna_tf32(p * gelu_t(d[mt][nt][h * 2 + 0] + bu[nl]));
                    v.y = rna_tf32(p * gelu_t(d[mt][nt][h * 2 + 1] + bu[nl + 1]));
                    *(float2*)(dst + nl) = v;
                }
            }
    } else {
#pragma unroll
        for (int mt = 0; mt < 4; mt++)
#pragma unroll
            for (int h = 0; h < 2; h++) {
                int rl = wm * 64 + mt * 16 + h * 8 + g;
                const float4* pp = (const float4*)(probs + (size_t)(m0 + rl) * 8);
                float4 p0 = pp[0], p1 = pp[1];
                const float* xr = xres + (size_t)(m0 + rl) * DIM + n0;
                float* dst = outp + (size_t)(m0 + rl) * DIM + n0;
#pragma unroll
                for (int nt = 0; nt < 8; nt++) {
                    int nl = wn * 64 + nt * 8 + i4 * 2;
                    float s0 = d[mt][nt][h * 2 + 0];
                    float s1 = d[mt][nt][h * 2 + 1];
#pragma unroll
                    for (int e = 0; e < 8; e++) {
                        float pe = (e == 0) ? p0.x : (e == 1) ? p0.y : (e == 2) ? p0.z :
                                   (e == 3) ? p0.w : (e == 4) ? p1.x : (e == 5) ? p1.y :
                                   (e == 6) ? p1.z : p1.w;
                        const float* bd = bias + (size_t)e * DIM + n0 + nl;
                        s0 += pe * bd[0];
                        s1 += pe * bd[1];
                    }
                    float2 xv = *(const float2*)(xr + nl);
                    float2 v; v.x = s0 + xv.x; v.y = s1 + xv.y;
                    *(float2*)(dst + nl) = v;
                }
            }
    }
}

// ---------------- launch ----------------
extern "C" void kernel_launch(void* const* d_in, const int* in_sizes, int n_in,
                              void* d_out, int out_size) {
    const float* x  = (const float*)d_in[0];
    const float* Wr = (const float*)d_in[1];
    const float* br = (const float*)d_in[2];
    const float* Wu = (const float*)d_in[3];
    const float* bu = (const float*)d_in[4];
    const float* Wd = (const float*)d_in[5];
    const float* bd = (const float*)d_in[6];
    float* out = (float*)d_out;

    float *Xr, *WuT, *WdT, *Hs, *Pr;
    cudaGetSymbolAddress((void**)&Xr,  g_Xr);
    cudaGetSymbolAddress((void**)&WuT, g_WuT);
    cudaGetSymbolAddress((void**)&WdT, g_WdT);
    cudaGetSymbolAddress((void**)&Hs,  g_Hs);
    cudaGetSymbolAddress((void**)&Pr,  g_Pr);

    cudaFuncSetAttribute(moe_gemm<0>, cudaFuncAttributeMaxDynamicSharedMemorySize, SMEM_SZ);
    cudaFuncSetAttribute(moe_gemm<1>, cudaFuncAttributeMaxDynamicSharedMemorySize, SMEM_SZ);
    cudaFuncSetAttribute(router_kernel, cudaFuncAttributeMaxDynamicSharedMemorySize, RTR_SMEM);

    // 1. rna(x)
    rna_copy_kernel<<<2048, 256>>>(x, Xr, (TOK * DIM) / 4);
    // 2. WuT[e][f][d] = rna(Wu[e][d][f])
    transpose_rna_kernel<<<dim3(EDIM / 32, DIM / 32, NEXP), dim3(32, 8)>>>(
        Wu, WuT, DIM, EDIM, (size_t)DIM * EDIM, (size_t)EDIM * DIM, DIM);
    // 3. WdT[n][e*1024+f] = rna(Wd[e][f][n])
    transpose_rna_kernel<<<dim3(DIM / 32, EDIM / 32, NEXP), dim3(32, 8)>>>(
        Wd, WdT, EDIM, DIM, (size_t)EDIM * DIM, (size_t)EDIM, KFLAT);
    // 4. router probs
    router_kernel<<<TOK / 8, 256, RTR_SMEM>>>(x, Wr, br, Pr);
    // 5. up-GEMM + gelu + p -> Hs
    moe_gemm<0><<<dim3(KFLAT / 128, TOK / 256), 256, SMEM_SZ>>>(
        Xr, WuT, DIM, Pr, bu, nullptr, Hs);
    // 6. down-GEMM + bias + residual -> out
    moe_gemm<1><<<dim3(DIM / 128, TOK / 256), 256, SMEM_SZ>>>(
        Hs, WdT, KFLAT, Pr, bd, x, out);
}

// round 12
// speedup vs baseline: 1.9068x; 1.9068x over previous
#include <cuda_runtime.h>
#include <cuda_fp16.h>
#include <cstdint>
#include <math.h>

#define TOK   8192
#define DIM   2048
#define NEXP  8
#define EDIM  1024
#define KFLAT 8192

// ---------------- static device scratch ----------------
__device__ __half g_Xh  [(size_t)TOK * DIM];          // fp16(x)
__device__ __half g_WuTh[(size_t)NEXP * EDIM * DIM];  // [e][f][d] fp16
__device__ __half g_WdTh[(size_t)DIM * KFLAT];        // [n][e*1024+f] fp16
__device__ __half g_Hsh [(size_t)TOK * KFLAT];        // fp16(p*gelu(..))
__device__ float  g_Pr  [(size_t)TOK * NEXP];

// ---------------- helpers ----------------
__device__ __forceinline__ uint32_t smem_u32(const void* p) {
    uint32_t a;
    asm("{ .reg .u64 t; cvta.to.shared.u64 t, %1; cvt.u32.u64 %0, t; }" : "=r"(a) : "l"(p));
    return a;
}
__device__ __forceinline__ float gelu_t(float h) {
    float u  = 0.7978845608028654f * (h + 0.044715f * h * h * h);
    float ex = __expf(2.0f * u);
    float th = 1.0f - __fdividef(2.0f, ex + 1.0f);
    return 0.5f * h * (1.0f + th);
}
__device__ __forceinline__ void cpasync16(uint32_t dst, const void* src) {
    asm volatile("cp.async.cg.shared.global [%0], [%1], 16;" :: "r"(dst), "l"(src));
}
__device__ __forceinline__ void ldsm4(uint32_t* r, uint32_t a) {
    asm volatile("ldmatrix.sync.aligned.m8n8.x4.shared.b16 {%0,%1,%2,%3}, [%4];"
                 : "=r"(r[0]), "=r"(r[1]), "=r"(r[2]), "=r"(r[3]) : "r"(a));
}
// m16n8k16 fp16 inputs, fp32 accumulate
__device__ __forceinline__ void mma16(float* d, const uint32_t* a, uint32_t b0, uint32_t b1) {
    asm volatile(
        "mma.sync.aligned.m16n8k16.row.col.f32.f16.f16.f32 "
        "{%0,%1,%2,%3}, {%4,%5,%6,%7}, {%8,%9}, {%0,%1,%2,%3};"
        : "+f"(d[0]), "+f"(d[1]), "+f"(d[2]), "+f"(d[3])
        : "r"(a[0]), "r"(a[1]), "r"(a[2]), "r"(a[3]), "r"(b0), "r"(b1));
}

// ---------------- prep kernels ----------------
// fp32 -> fp16 copy (pairs)
__global__ void h_copy_kernel(const float* __restrict__ in, __half2* __restrict__ out, int n2) {
    int i = blockIdx.x * blockDim.x + threadIdx.x;
    int st = gridDim.x * blockDim.x;
    const float2* i2 = (const float2*)in;
    for (; i < n2; i += st) {
        float2 v = i2[i];
        out[i] = __floats2half2_rn(v.x, v.y);
    }
}

// out[z*outE + c*outRow + r] = fp16(in[z*inE + r*C + c])
__global__ void transpose_h_kernel(const float* __restrict__ in, __half* __restrict__ out,
                                   int R, int C, size_t inE, size_t outE, int outRow) {
    __shared__ float tile[32][33];
    const float* ip = in + (size_t)blockIdx.z * inE;
    __half* op = out + (size_t)blockIdx.z * outE;
    int c0 = blockIdx.x * 32, r0 = blockIdx.y * 32;
#pragma unroll
    for (int i = threadIdx.y; i < 32; i += 8)
        tile[i][threadIdx.x] = ip[(size_t)(r0 + i) * C + c0 + threadIdx.x];
    __syncthreads();
#pragma unroll
    for (int i = threadIdx.y; i < 32; i += 8)
        op[(size_t)(c0 + i) * outRow + r0 + threadIdx.x] = __float2half_rn(tile[threadIdx.x][i]);
}

// router with Wr cached in smem (pad-9 layout, conflict-free)
#define RTR_SMEM (2048 * 9 * 4)
__global__ void router_kernel(const float* __restrict__ x, const float* __restrict__ Wr,
                              const float* __restrict__ br, float* __restrict__ probs) {
    extern __shared__ float ws[];
    int tid = threadIdx.x;
    for (int i = tid; i < DIM * 8; i += 256) {
        int k = i >> 3, e = i & 7;
        ws[k * 9 + e] = Wr[i];
    }
    __syncthreads();
    int t = blockIdx.x * 8 + (tid >> 5);
    int lid = tid & 31;
    const float* xr = x + (size_t)t * DIM;
    float acc[8];
#pragma unroll
    for (int e = 0; e < 8; e++) acc[e] = 0.f;
    for (int k = lid; k < DIM; k += 32) {
        float xv = xr[k];
        const float* w = ws + k * 9;
#pragma unroll
        for (int e = 0; e < 8; e++) acc[e] += xv * w[e];
    }
#pragma unroll
    for (int e = 0; e < 8; e++)
#pragma unroll
        for (int o = 16; o > 0; o >>= 1) acc[e] += __shfl_xor_sync(0xffffffffu, acc[e], o);
    if (lid == 0) {
        float m = -1e30f;
#pragma unroll
        for (int e = 0; e < 8; e++) { acc[e] += br[e]; m = fmaxf(m, acc[e]); }
        float s = 0.f;
#pragma unroll
        for (int e = 0; e < 8; e++) { acc[e] = expf(acc[e] - m); s += acc[e]; }
        float inv = 1.f / s;
#pragma unroll
        for (int e = 0; e < 8; e++) probs[(size_t)t * 8 + e] = acc[e] * inv;
    }
}

// ---------------- fp16 mma.sync GEMM ----------------
// CTA tile 256(M) x 128(N), 512 threads = 16 warps (4x4), warp tile 64x32.
// K staged 64 halves/iter (128B rows + 16B pad = 144B stride),
// 4 kk-steps of k16 per iter, 4-stage cp.async pipeline (wait_group 2).
// stage: A 256*144 = 36864B + B 128*144 = 18432B = 55296B
#define STG_B     55296
#define SMEM_SZ   221184     // 4 * 55296

// MODE 0: Hsh = fp16(p[t,e0] * gelu(A@B^T + bu))  A=Xh, B=WuTh rows, out half
// MODE 1: out = A@B^T + sum_e p_e*bd_e + x        A=Hsh, B=WdTh rows, out float
template<int MODE>
__global__ void __launch_bounds__(512, 1) moe_gemm(
    const __half* __restrict__ A, const __half* __restrict__ Bm, int K,
    const float* __restrict__ probs, const float* __restrict__ bias,
    const float* __restrict__ xres, void* __restrict__ outp)
{
    extern __shared__ float smem[];
    uint32_t sb = smem_u32(smem);
    const int tid = threadIdx.x, wid = tid >> 5, lid = tid & 31;
    const int wm = wid & 3, wn = wid >> 2;          // warp grid 4(M) x 4(N)
    const int m0 = blockIdx.y * 256, n0 = blockIdx.x * 128;
    const int g = lid >> 2, i4 = lid & 3;

    // ---- per-thread ldmatrix smem byte offsets within a stage ----
    // A: groups (rows0-7,b0)(rows8-15,b0)(rows0-7,b16)(rows8-15,b16) -> a0..a3
    const uint32_t aoff = (uint32_t)((wm * 64 + (lid & 15)) * 144 + ((lid >> 4) * 16));
    // B: groups (n0-7,b0)(n0-7,b16)(n8-15,b0)(n8-15,b16) -> b0,b1 per n8 group
    const uint32_t boff = (uint32_t)(36864 +
        (wn * 32 + ((lid >> 4) & 1) * 8 + (lid & 7)) * 144 + (((lid >> 3) & 1) * 16));

    float d[4][4][4];
#pragma unroll
    for (int a = 0; a < 4; a++)
#pragma unroll
        for (int b = 0; b < 4; b++)
#pragma unroll
            for (int c = 0; c < 4; c++) d[a][b][c] = 0.f;

    const __half* Ab = A + (size_t)m0 * K;
    const __half* Bb = Bm + (size_t)n0 * K;

    // loader: 3072 16B chunks per stage (A 2048, B 1024), 6 per thread
    auto load_stage = [&](int st, int kt) {
        uint32_t base = sb + st * STG_B;
        const __half* Ag = Ab + kt * 64;
        const __half* Bg = Bb + kt * 64;
#pragma unroll
        for (int q = 0; q < 6; q++) {
            int ci = q * 512 + tid;
            if (ci < 2048) {
                int r = ci >> 3, c = ci & 7;
                cpasync16(base + r * 144 + c * 16, Ag + (size_t)r * K + c * 8);
            } else {
                int c2 = ci - 2048;
                int r = c2 >> 3, c = c2 & 7;
                cpasync16(base + 36864 + r * 144 + c * 16, Bg + (size_t)r * K + c * 8);
            }
        }
    };

    const int iters = K >> 6;
    load_stage(0, 0);
    asm volatile("cp.async.commit_group;" ::: "memory");
    load_stage(1, 1);
    asm volatile("cp.async.commit_group;" ::: "memory");
    load_stage(2, 2);
    asm volatile("cp.async.commit_group;" ::: "memory");

    for (int kt = 0; kt < iters; kt++) {
        asm volatile("cp.async.wait_group 2;" ::: "memory");
        __syncthreads();
        if (kt + 3 < iters) {
            load_stage((kt + 3) & 3, kt + 3);
        }
        asm volatile("cp.async.commit_group;" ::: "memory");

        uint32_t base = sb + (kt & 3) * STG_B;
#pragma unroll
        for (int kk = 0; kk < 4; kk++) {           // kk = one k16 slice (32 bytes)
            uint32_t af[4][4], bf[2][4];
#pragma unroll
            for (int mt = 0; mt < 4; mt++)
                ldsm4(af[mt], base + aoff + mt * (16 * 144) + kk * 32);
#pragma unroll
            for (int P = 0; P < 2; P++)
                ldsm4(bf[P], base + boff + P * (16 * 144) + kk * 32);
#pragma unroll
            for (int mt = 0; mt < 4; mt++)
#pragma unroll
                for (int P = 0; P < 2; P++) {
                    mma16(d[mt][2 * P],     af[mt], bf[P][0], bf[P][1]);
                    mma16(d[mt][2 * P + 1], af[mt], bf[P][2], bf[P][3]);
                }
        }
    }

    // ---- epilogue ----
    if (MODE == 0) {
        __half* outh = (__half*)outp;
        int e0 = n0 >> 10;
#pragma unroll
        for (int mt = 0; mt < 4; mt++)
#pragma unroll
            for (int h = 0; h < 2; h++) {
                int rl = wm * 64 + mt * 16 + h * 8 + g;
                float p = probs[(size_t)(m0 + rl) * 8 + e0];
                __half* dst = outh + (size_t)(m0 + rl) * KFLAT + n0;
                const float* bu = bias + (size_t)e0 * EDIM + (n0 & 1023);
#pragma unroll
                for (int nt = 0; nt < 4; nt++) {
                    int nl = wn * 32 + nt * 8 + i4 * 2;
                    float v0 = p * gelu_t(d[mt][nt][h * 2 + 0] + bu[nl]);
                    float v1 = p * gelu_t(d[mt][nt][h * 2 + 1] + bu[nl + 1]);
                    *(__half2*)(dst + nl) = __floats2half2_rn(v0, v1);
                }
            }
    } else {
        float* outf = (float*)outp;
#pragma unroll
        for (int mt = 0; mt < 4; mt++)
#pragma unroll
            for (int h = 0; h < 2; h++) {
                int rl = wm * 64 + mt * 16 + h * 8 + g;
                const float4* pp = (const float4*)(probs + (size_t)(m0 + rl) * 8);
                float4 p0 = pp[0], p1 = pp[1];
                const float* xr = xres + (size_t)(m0 + rl) * DIM + n0;
                float* dst = outf + (size_t)(m0 + rl) * DIM + n0;
#pragma unroll
                for (int nt = 0; nt < 4; nt++) {
                    int nl = wn * 32 + nt * 8 + i4 * 2;
                    float s0 = d[mt][nt][h * 2 + 0];
                    float s1 = d[mt][nt][h * 2 + 1];
#pragma unroll
                    for (int e = 0; e < 8; e++) {
                        float pe = (e == 0) ? p0.x : (e == 1) ? p0.y : (e == 2) ? p0.z :
                                   (e == 3) ? p0.w : (e == 4) ? p1.x : (e == 5) ? p1.y :
                                   (e == 6) ? p1.z : p1.w;
                        const float* bd = bias + (size_t)e * DIM + n0 + nl;
                        s0 += pe * bd[0];
                        s1 += pe * bd[1];
                    }
                    float2 xv = *(const float2*)(xr + nl);
                    float2 v; v.x = s0 + xv.x; v.y = s1 + xv.y;
                    *(float2*)(dst + nl) = v;
                }
            }
    }
}

// ---------------- launch ----------------
extern "C" void kernel_launch(void* const* d_in, const int* in_sizes, int n_in,
                              void* d_out, int out_size) {
    const float* x  = (const float*)d_in[0];
    const float* Wr = (const float*)d_in[1];
    const float* br = (const float*)d_in[2];
    const float* Wu = (const float*)d_in[3];
    const float* bu = (const float*)d_in[4];
    const float* Wd = (const float*)d_in[5];
    const float* bd = (const float*)d_in[6];
    float* out = (float*)d_out;

    __half *Xh, *WuTh, *WdTh, *Hsh;
    float *Pr;
    cudaGetSymbolAddress((void**)&Xh,   g_Xh);
    cudaGetSymbolAddress((void**)&WuTh, g_WuTh);
    cudaGetSymbolAddress((void**)&WdTh, g_WdTh);
    cudaGetSymbolAddress((void**)&Hsh,  g_Hsh);
    cudaGetSymbolAddress((void**)&Pr,   g_Pr);

    cudaFuncSetAttribute(moe_gemm<0>, cudaFuncAttributeMaxDynamicSharedMemorySize, SMEM_SZ);
    cudaFuncSetAttribute(moe_gemm<1>, cudaFuncAttributeMaxDynamicSharedMemorySize, SMEM_SZ);
    cudaFuncSetAttribute(router_kernel, cudaFuncAttributeMaxDynamicSharedMemorySize, RTR_SMEM);

    // 1. fp16(x)
    h_copy_kernel<<<2048, 256>>>(x, (__half2*)Xh, (TOK * DIM) / 2);
    // 2. WuTh[e][f][d] = fp16(Wu[e][d][f])
    transpose_h_kernel<<<dim3(EDIM / 32, DIM / 32, NEXP), dim3(32, 8)>>>(
        Wu, WuTh, DIM, EDIM, (size_t)DIM * EDIM, (size_t)EDIM * DIM, DIM);
    // 3. WdTh[n][e*1024+f] = fp16(Wd[e][f][n])
    transpose_h_kernel<<<dim3(DIM / 32, EDIM / 32, NEXP), dim3(32, 8)>>>(
        Wd, WdTh, EDIM, DIM, (size_t)EDIM * DIM, (size_t)EDIM, KFLAT);
    // 4. router probs
    router_kernel<<<TOK / 8, 256, RTR_SMEM>>>(x, Wr, br, Pr);
    // 5. up-GEMM + gelu + p -> Hsh (fp16)
    moe_gemm<0><<<dim3(KFLAT / 128, TOK / 256), 512, SMEM_SZ>>>(
        Xh, WuTh, DIM, Pr, bu, nullptr, Hsh);
    // 6. down-GEMM + bias + residual -> out (fp32)
    moe_gemm<1><<<dim3(DIM / 128, TOK / 256), 512, SMEM_SZ>>>(
        Hsh, WdTh, KFLAT, Pr, bd, x, out);
}